// round 1
// baseline (speedup 1.0000x reference)
#include <cuda_runtime.h>
#include <math.h>

// Problem dims
#define B_   4
#define CIN  256
#define CO   128
#define HIN  64
#define WIN  64
#define H2   128
#define W2   128

// Scratch (device globals; no allocations allowed)
__device__ float g_y[B_ * CO * H2 * W2];        // conv-transpose output (33.5 MB)
__device__ float g_kf[B_ * 9 * H2 * W2];        // adaptive kernel factors
__device__ float g_w1r[4 * 4 * CIN * CO];       // [pq][t][ci][co]
__device__ float g_w2r[CO * 9 * CO];            // [c][t][co]

// ---------------------------------------------------------------------------
// Weight rearrangement for conv-transpose.
// y[oh,ow] gets x[ih,iw] * w1[ci][co][kh][kw] with oh = 2*ih + kh - 1.
// Parity p = oh&1:  p=0: (th=0 -> kh=1, dh=0), (th=1 -> kh=3, dh=-1)
//                   p=1: (th=0 -> kh=2, dh=0), (th=1 -> kh=0, dh=+1)
// ---------------------------------------------------------------------------
__global__ void prep_w1(const float* __restrict__ w1) {
    int idx = blockIdx.x * blockDim.x + threadIdx.x;
    if (idx >= 16 * CIN * CO) return;
    int co = idx & 127;
    int ci = (idx >> 7) & 255;
    int t  = (idx >> 15) & 3;
    int pq = idx >> 17;
    int p = pq >> 1, q = pq & 1;
    int th = t >> 1, tw = t & 1;
    int kh = (p == 0) ? (th == 0 ? 1 : 3) : (th == 0 ? 2 : 0);
    int kw = (q == 0) ? (tw == 0 ? 1 : 3) : (tw == 0 ? 2 : 0);
    g_w1r[idx] = w1[((ci * CO + co) * 4 + kh) * 4 + kw];
}

// wk[co][c][i][j] = w2[c][co][2-i][2-j];  store as [c][t=i*3+j][co]
__global__ void prep_w2(const float* __restrict__ w2) {
    int idx = blockIdx.x * blockDim.x + threadIdx.x;
    if (idx >= CO * 9 * CO) return;
    int co = idx & 127;
    int t  = (idx >> 7) % 9;
    int c  = idx / (9 * 128);
    int di = t / 3, dj = t % 3;
    g_w2r[idx] = w2[((c * CO + co) * 3 + (2 - di)) * 3 + (2 - dj)];
}

// ---------------------------------------------------------------------------
// Conv-transpose as per-parity 2x2-tap implicit GEMM.
// Block: 256 threads, tile = 128 co x (2 rows x 64 cols of input-space pixels).
// Thread: 8 co x 8 pixels register tile. K loop over Cin in chunks of 8.
// ---------------------------------------------------------------------------
__global__ __launch_bounds__(256) void conv1_kernel(
    const float* __restrict__ x, const float* __restrict__ b1)
{
    __shared__ __align__(16) float xs[8][3][66];
    __shared__ __align__(16) float ws[8][4][128];

    const int pq = blockIdx.y;
    const int p = pq >> 1, q = pq & 1;
    const int b = blockIdx.z;
    const int i0 = blockIdx.x * 2;

    const int tid = threadIdx.x;
    const int ty = tid >> 4, tx = tid & 15;
    const int lr = tx >> 3, lc0 = (tx & 7) * 8;
    const int co0 = ty * 8;

    float acc[8][8];
#pragma unroll
    for (int k = 0; k < 8; k++)
#pragma unroll
        for (int px = 0; px < 8; px++) acc[k][px] = 0.f;

    const float* xb = x + (size_t)b * CIN * HIN * WIN;
    const float* wbase = g_w1r + (size_t)pq * 4 * CIN * CO;

    const int rb = i0 + p - 1;     // shared row s -> global row rb+s
    const int cb = q - 1;          // shared col s -> global col cb+s

    for (int c0 = 0; c0 < CIN; c0 += 8) {
        // stage x tile (3 rows x 66 cols per channel, zero-padded)
        for (int idx = tid; idx < 8 * 3 * 66; idx += 256) {
            int col = idx % 66;
            int tmp = idx / 66;
            int r = tmp % 3;
            int cc = tmp / 3;
            int gr = rb + r, gc = cb + col;
            float v = 0.f;
            if ((unsigned)gr < HIN && (unsigned)gc < WIN)
                v = xb[(size_t)(c0 + cc) * HIN * WIN + gr * WIN + gc];
            xs[cc][r][col] = v;
        }
        // stage weights [cc][t][co]
        for (int idx = tid; idx < 8 * 4 * 128; idx += 256) {
            int co = idx & 127;
            int t  = (idx >> 7) & 3;
            int cc = idx >> 9;
            ws[cc][t][co] = wbase[(size_t)t * CIN * CO + (c0 + cc) * CO + co];
        }
        __syncthreads();

#pragma unroll
        for (int cc = 0; cc < 8; cc++) {
#pragma unroll
            for (int th = 0; th < 2; th++) {
                const int srow = lr + (p == 0 ? 1 - th : th);
                float yv[9];
#pragma unroll
                for (int m = 0; m < 9; m++) yv[m] = xs[cc][srow][lc0 + m];
#pragma unroll
                for (int tw = 0; tw < 2; tw++) {
                    const int t = th * 2 + tw;
                    float4 a0 = *(const float4*)&ws[cc][t][co0];
                    float4 a1 = *(const float4*)&ws[cc][t][co0 + 4];
                    float wv[8] = {a0.x, a0.y, a0.z, a0.w, a1.x, a1.y, a1.z, a1.w};
                    const int off = (q == 0 ? 1 - tw : tw);
#pragma unroll
                    for (int px = 0; px < 8; px++) {
                        float xv = yv[px + off];
#pragma unroll
                        for (int k = 0; k < 8; k++)
                            acc[k][px] = fmaf(wv[k], xv, acc[k][px]);
                    }
                }
            }
        }
        __syncthreads();
    }

    // store into y (standard NCHW layout, strided by parity)
    float* yb = g_y + (size_t)b * CO * H2 * W2;
    const int oh = 2 * (i0 + lr) + p;
#pragma unroll
    for (int k = 0; k < 8; k++) {
        float bv = b1[co0 + k];
        float* row = yb + (size_t)(co0 + k) * H2 * W2 + oh * W2;
#pragma unroll
        for (int px = 0; px < 8; px++) {
            int ow = 2 * (lc0 + px) + q;
            row[ow] = acc[k][px] + bv;
        }
    }
}

// ---------------------------------------------------------------------------
// Adaptive kernel factors: kfac[b][t][h][w] = exp(-0.5 * sum_c (g_n - g)^2),
// zero for out-of-range neighbors (their y contribution is zero anyway).
// ---------------------------------------------------------------------------
__global__ __launch_bounds__(256) void kfac_kernel(const float* __restrict__ guide) {
    __shared__ float gs[8][18][18];
    const int b = blockIdx.z;
    const int h0 = blockIdx.y * 16, w0 = blockIdx.x * 16;
    const int tid = threadIdx.x;
    const int ly = tid >> 4, lx = tid & 15;

    float s[9];
#pragma unroll
    for (int t = 0; t < 9; t++) s[t] = 0.f;

    const float* gb = guide + (size_t)b * CO * H2 * W2;

    for (int c0 = 0; c0 < CO; c0 += 8) {
        for (int idx = tid; idx < 8 * 18 * 18; idx += 256) {
            int col = idx % 18;
            int tmp = idx / 18;
            int r = tmp % 18;
            int cc = tmp / 18;
            int gr = h0 - 1 + r, gc = w0 - 1 + col;
            float v = 0.f;
            if ((unsigned)gr < H2 && (unsigned)gc < W2)
                v = gb[(size_t)(c0 + cc) * H2 * W2 + gr * W2 + gc];
            gs[cc][r][col] = v;
        }
        __syncthreads();
#pragma unroll
        for (int cc = 0; cc < 8; cc++) {
            float g0 = gs[cc][ly + 1][lx + 1];
#pragma unroll
            for (int di = 0; di < 3; di++)
#pragma unroll
                for (int dj = 0; dj < 3; dj++) {
                    float d = gs[cc][ly + di][lx + dj] - g0;
                    s[di * 3 + dj] = fmaf(d, d, s[di * 3 + dj]);
                }
        }
        __syncthreads();
    }

    const int h = h0 + ly, w = w0 + lx;
    float* kb = g_kf + (size_t)b * 9 * H2 * W2;
#pragma unroll
    for (int t = 0; t < 9; t++) {
        int nh = h + t / 3 - 1, nw = w + t % 3 - 1;
        float v = ((unsigned)nh < H2 && (unsigned)nw < W2) ? expf(-0.5f * s[t]) : 0.f;
        kb[(size_t)t * H2 * W2 + h * W2 + w] = v;
    }
}

// ---------------------------------------------------------------------------
// PAC conv: out[co,pix] = b2 + sum_t sum_c W_t[c,co] * (y[c, pix+off_t] * kf[t,pix])
// Block: 128 co x (2 rows x 64 cols), thread 8co x 8pix, C chunk = 4.
// ---------------------------------------------------------------------------
__global__ __launch_bounds__(256) void pac_kernel(
    const float* __restrict__ b2, float* __restrict__ out)
{
    __shared__ __align__(16) float ys[4][4][66];
    __shared__ __align__(16) float ws2[4][9][128];
    __shared__ __align__(16) float kfs[9][128];

    const int b = blockIdx.z;
    const int h0 = blockIdx.y * 2, w0 = blockIdx.x * 64;
    const int tid = threadIdx.x;
    const int ty = tid >> 4, tx = tid & 15;
    const int lr = tx >> 3, lc0 = (tx & 7) * 8;
    const int co0 = ty * 8;

    // stage kfac for this tile (used for whole kernel)
    const float* kb = g_kf + (size_t)b * 9 * H2 * W2;
    for (int idx = tid; idx < 9 * 128; idx += 256) {
        int pix = idx & 127;
        int t = idx >> 7;
        int r = pix >> 6, cc = pix & 63;
        kfs[t][pix] = kb[(size_t)t * H2 * W2 + (h0 + r) * W2 + w0 + cc];
    }

    float acc[8][8];
#pragma unroll
    for (int k = 0; k < 8; k++)
#pragma unroll
        for (int px = 0; px < 8; px++) acc[k][px] = 0.f;

    const float* yb = g_y + (size_t)b * CO * H2 * W2;

    for (int c0 = 0; c0 < CO; c0 += 4) {
        // stage y tile (4 rows x 66 cols per channel, zero-padded)
        for (int idx = tid; idx < 4 * 4 * 66; idx += 256) {
            int col = idx % 66;
            int tmp = idx / 66;
            int r = tmp & 3;
            int cc = tmp >> 2;
            int gr = h0 - 1 + r, gc = w0 - 1 + col;
            float v = 0.f;
            if ((unsigned)gr < H2 && (unsigned)gc < W2)
                v = yb[(size_t)(c0 + cc) * H2 * W2 + gr * W2 + gc];
            ys[cc][r][col] = v;
        }
        // stage weights: contiguous [c][t][co] chunk
        for (int idx = tid; idx < 4 * 9 * 128; idx += 256)
            ((float*)ws2)[idx] = g_w2r[(size_t)c0 * 9 * 128 + idx];
        __syncthreads();

#pragma unroll
        for (int di = 0; di < 3; di++) {
            float kfA[3][8];
#pragma unroll
            for (int dj = 0; dj < 3; dj++)
#pragma unroll
                for (int px = 0; px < 8; px++)
                    kfA[dj][px] = kfs[di * 3 + dj][lr * 64 + lc0 + px];
#pragma unroll
            for (int cc = 0; cc < 4; cc++) {
                float yv[10];
#pragma unroll
                for (int m = 0; m < 10; m++) yv[m] = ys[cc][lr + di][lc0 + m];
#pragma unroll
                for (int dj = 0; dj < 3; dj++) {
                    float4 a0 = *(const float4*)&ws2[cc][di * 3 + dj][co0];
                    float4 a1 = *(const float4*)&ws2[cc][di * 3 + dj][co0 + 4];
                    float wv[8] = {a0.x, a0.y, a0.z, a0.w, a1.x, a1.y, a1.z, a1.w};
                    float tmp[8];
#pragma unroll
                    for (int px = 0; px < 8; px++)
                        tmp[px] = yv[px + dj] * kfA[dj][px];
#pragma unroll
                    for (int px = 0; px < 8; px++)
#pragma unroll
                        for (int k = 0; k < 8; k++)
                            acc[k][px] = fmaf(wv[k], tmp[px], acc[k][px]);
                }
            }
        }
        __syncthreads();
    }

    // store
    const int h = h0 + lr;
    float* ob = out + (size_t)b * CO * H2 * W2;
#pragma unroll
    for (int k = 0; k < 8; k++) {
        float bv = b2[co0 + k];
        float4 v0, v1;
        v0.x = acc[k][0] + bv; v0.y = acc[k][1] + bv;
        v0.z = acc[k][2] + bv; v0.w = acc[k][3] + bv;
        v1.x = acc[k][4] + bv; v1.y = acc[k][5] + bv;
        v1.z = acc[k][6] + bv; v1.w = acc[k][7] + bv;
        float* dst = ob + (size_t)(co0 + k) * H2 * W2 + h * W2 + w0 + lc0;
        *(float4*)dst = v0;
        *(float4*)(dst + 4) = v1;
    }
}

// ---------------------------------------------------------------------------
extern "C" void kernel_launch(void* const* d_in, const int* in_sizes, int n_in,
                              void* d_out, int out_size)
{
    const float* x     = (const float*)d_in[0];
    const float* guide = (const float*)d_in[1];
    const float* w1    = (const float*)d_in[2];
    const float* b1    = (const float*)d_in[3];
    const float* w2    = (const float*)d_in[4];
    const float* b2    = (const float*)d_in[5];
    float* out = (float*)d_out;

    prep_w1<<<(16 * CIN * CO + 255) / 256, 256>>>(w1);
    prep_w2<<<(CO * 9 * CO + 255) / 256, 256>>>(w2);
    conv1_kernel<<<dim3(32, 4, 4), 256>>>(x, b1);
    kfac_kernel<<<dim3(8, 8, 4), 256>>>(guide);
    pac_kernel<<<dim3(2, 64, 4), 256>>>(b2, out);
}

// round 8
// speedup vs baseline: 3.5889x; 3.5889x over previous
#include <cuda_runtime.h>
#include <math.h>
#include <stdint.h>

// Problem dims
#define B_   4
#define CIN  256
#define CO   128
#define HIN  64
#define WIN  64
#define H2   128
#define W2   128
#define HW2  (H2 * W2)

// Scratch (device globals)
__device__ float    g_y[B_ * CO * H2 * W2];     // conv-transpose output
__device__ float    g_kf[B_ * 9 * H2 * W2];     // adaptive kernel factors
__device__ uint32_t g_w1s[4 * 4 * 8 * 4096];    // conv1 A tiles: [pq][t][cch][co*32+swz(k)] tf32
__device__ uint32_t g_w2s[9 * 4 * 4096];        // pac   A tiles: [t][cch][co*32+swz(k)]  tf32

// ---------------------------------------------------------------------------
// helpers
// ---------------------------------------------------------------------------
__device__ __forceinline__ uint32_t f2tf32(float v) {
    uint32_t o;
    asm("cvt.rn.tf32.f32 %0, %1;" : "=r"(o) : "f"(v));
    return o;
}
__device__ __forceinline__ void mma_tf32(float* d, const uint32_t* a, const uint32_t* b) {
    asm volatile(
        "mma.sync.aligned.m16n8k8.row.col.f32.tf32.tf32.f32 "
        "{%0,%1,%2,%3}, {%4,%5,%6,%7}, {%8,%9}, {%0,%1,%2,%3};"
        : "+f"(d[0]), "+f"(d[1]), "+f"(d[2]), "+f"(d[3])
        : "r"(a[0]), "r"(a[1]), "r"(a[2]), "r"(a[3]), "r"(b[0]), "r"(b[1]));
}
// A swizzle: phys float index within a 128x32 tile
__device__ __forceinline__ int a_idx(int co, int k) {
    return co * 32 + (((k >> 2) ^ (co & 7)) << 2) + (k & 3);
}
// B swizzle: phys float index within a 32x128 (k-major) tile
__device__ __forceinline__ int b_idx(int k, int pix) {
    return k * 128 + ((((pix >> 2) ^ (k & 7))) << 2) + (pix & 3);
}

// ---------------------------------------------------------------------------
// prep_w1s: conv1 weights -> tf32, tiled+swizzled.
// tap t=(th,tw); parity pq=(p,q); kh/kw per transpose-conv parity decomposition.
// ---------------------------------------------------------------------------
__global__ void prep_w1s(const float* __restrict__ w1) {
    int idx = blockIdx.x * blockDim.x + threadIdx.x;
    if (idx >= 16 * CIN * CO) return;
    int co = idx & 127;
    int ci = (idx >> 7) & 255;
    int t  = (idx >> 15) & 3;
    int pq = idx >> 17;
    int p = pq >> 1, q = pq & 1;
    int th = t >> 1, tw = t & 1;
    int kh = (p == 0) ? (th == 0 ? 1 : 3) : (th == 0 ? 2 : 0);
    int kw = (q == 0) ? (tw == 0 ? 1 : 3) : (tw == 0 ? 2 : 0);
    float v = w1[((ci * CO + co) * 4 + kh) * 4 + kw];
    int k = ci & 31, cch = ci >> 5;
    g_w1s[(size_t)(((pq * 4 + t) * 8) + cch) * 4096 + a_idx(co, k)] = f2tf32(v);
}

// prep_w2s: pac weights wk[co][ci][di][dj] = w2[ci][co][2-di][2-dj]
__global__ void prep_w2s(const float* __restrict__ w2) {
    int idx = blockIdx.x * blockDim.x + threadIdx.x;
    if (idx >= 9 * 128 * 128) return;
    int co = idx & 127;
    int ci = (idx >> 7) & 127;
    int t  = idx >> 14;
    int di = t / 3, dj = t % 3;
    float v = w2[((ci * CO + co) * 3 + (2 - di)) * 3 + (2 - dj)];
    int k = ci & 31, cch = ci >> 5;
    g_w2s[(size_t)(t * 4 + cch) * 4096 + a_idx(co, k)] = f2tf32(v);
}

// ---------------------------------------------------------------------------
// Shared GEMM compute step: one K=32 chunk, 8 warps (2 co-groups x 4 pix-groups)
// ---------------------------------------------------------------------------
__device__ __forceinline__ void gemm_chunk(
    const uint32_t* __restrict__ As, const uint32_t* __restrict__ Bs,
    float acc[4][4][4], int lane, int wm, int wn)
{
    const int row = lane >> 2;
    const int kk  = lane & 3;
#pragma unroll
    for (int ks = 0; ks < 4; ks++) {
        uint32_t af[4][4];
#pragma unroll
        for (int mt = 0; mt < 4; mt++) {
            int co = wm + mt * 16 + row;
            int sw0 = (((2 * ks) ^ (co & 7)) << 2);
            int sw1 = (((2 * ks + 1) ^ (co & 7)) << 2);
            af[mt][0] = As[co * 32 + sw0 + kk];
            af[mt][1] = As[(co + 8) * 32 + sw0 + kk];
            af[mt][2] = As[co * 32 + sw1 + kk];
            af[mt][3] = As[(co + 8) * 32 + sw1 + kk];
        }
        uint32_t bf[4][2];
        const int k0 = ks * 8 + kk;
        const int k1 = k0 + 4;
#pragma unroll
        for (int nt = 0; nt < 4; nt++) {
            int n = wn + nt * 8 + row;
            bf[nt][0] = Bs[k0 * 128 + (((n >> 2) ^ (k0 & 7)) << 2) + (n & 3)];
            bf[nt][1] = Bs[k1 * 128 + (((n >> 2) ^ (k1 & 7)) << 2) + (n & 3)];
        }
#pragma unroll
        for (int mt = 0; mt < 4; mt++)
#pragma unroll
            for (int nt = 0; nt < 4; nt++)
                mma_tf32(acc[mt][nt], af[mt], bf[nt]);
    }
}

// ---------------------------------------------------------------------------
// conv1: transpose-conv as per-parity tf32 MMA GEMM.
// Block: M=128 co x N=128 pix (2 rows x 64 cols, input space). K=4 taps x 256ci.
// ---------------------------------------------------------------------------
__global__ __launch_bounds__(256) void conv1_mma(
    const float* __restrict__ x, const float* __restrict__ b1)
{
    __shared__ __align__(16) uint32_t As[128 * 32];
    __shared__ __align__(16) uint32_t Bs[32 * 128];

    const int tid = threadIdx.x;
    const int lane = tid & 31, wid = tid >> 5;
    const int wm = (wid >> 2) * 64, wn = (wid & 3) * 32;
    const int pq = blockIdx.y;
    const int p = pq >> 1, q = pq & 1;
    const int b = blockIdx.z;
    const int i0 = blockIdx.x * 2;

    float acc[4][4][4];
#pragma unroll
    for (int mt = 0; mt < 4; mt++)
#pragma unroll
        for (int nt = 0; nt < 4; nt++)
#pragma unroll
            for (int r = 0; r < 4; r++) acc[mt][nt][r] = 0.f;

    const float* xb = x + (size_t)b * CIN * HIN * WIN;
    const int lq = tid & 31, wq = tid >> 5;   // staging: k = wq*4+j, pix = lq*4+i

    for (int t = 0; t < 4; t++) {
        const int th = t >> 1, tw = t & 1;
        const int di = (th == 0) ? 0 : (p == 0 ? -1 : 1);
        const int dj = (tw == 0) ? 0 : (q == 0 ? -1 : 1);
        for (int cch = 0; cch < 8; cch++) {
            // stage A: linear copy of pre-swizzled tile
            {
                const uint4* src = (const uint4*)(g_w1s + (size_t)((pq * 4 + t) * 8 + cch) * 4096);
                uint4* dst = (uint4*)As;
#pragma unroll
                for (int j = 0; j < 4; j++) dst[tid + j * 256] = src[tid + j * 256];
            }
            // stage B: tf32(x[ci][I+di][j+dj]) for 32 ci x 128 pix
            {
#pragma unroll
                for (int j = 0; j < 4; j++) {
                    const int k = wq * 4 + j;
                    const float* xrow = xb + (size_t)(cch * 32 + k) * HIN * WIN;
                    uint4 v;
                    uint32_t* vp = (uint32_t*)&v;
#pragma unroll
                    for (int i = 0; i < 4; i++) {
                        int pix = lq * 4 + i;
                        int gr = i0 + (pix >> 6) + di;
                        int gc = (pix & 63) + dj;
                        float xv = 0.f;
                        if ((unsigned)gr < HIN && (unsigned)gc < WIN)
                            xv = __ldg(xrow + gr * WIN + gc);
                        vp[i] = f2tf32(xv);
                    }
                    *(uint4*)&Bs[k * 128 + ((lq ^ (k & 7)) << 2)] = v;
                }
            }
            __syncthreads();
            gemm_chunk(As, Bs, acc, lane, wm, wn);
            __syncthreads();
        }
    }

    // epilogue -> g_y (strided by parity)
    float* yb = g_y + (size_t)b * CO * HW2;
    const int row = lane >> 2, col2 = (lane & 3) * 2;
#pragma unroll
    for (int mt = 0; mt < 4; mt++) {
        int co = wm + mt * 16 + row;
        float bv0 = __ldg(b1 + co);
        float bv1 = __ldg(b1 + co + 8);
#pragma unroll
        for (int nt = 0; nt < 4; nt++) {
            int pix = wn + nt * 8 + col2;
            int I = i0 + (pix >> 6), j = pix & 63;
            int oh = 2 * I + p, ow = 2 * j + q;
            float* d0 = yb + (size_t)co * HW2 + oh * W2 + ow;
            d0[0] = acc[mt][nt][0] + bv0;
            d0[2] = acc[mt][nt][1] + bv0;
            float* d1 = yb + (size_t)(co + 8) * HW2 + oh * W2 + ow;
            d1[0] = acc[mt][nt][2] + bv1;
            d1[2] = acc[mt][nt][3] + bv1;
        }
    }
}

// ---------------------------------------------------------------------------
// kfac (unchanged)
// ---------------------------------------------------------------------------
__global__ __launch_bounds__(256) void kfac_kernel(const float* __restrict__ guide) {
    __shared__ float gs[8][18][18];
    const int b = blockIdx.z;
    const int h0 = blockIdx.y * 16, w0 = blockIdx.x * 16;
    const int tid = threadIdx.x;
    const int ly = tid >> 4, lx = tid & 15;

    float s[9];
#pragma unroll
    for (int t = 0; t < 9; t++) s[t] = 0.f;

    const float* gb = guide + (size_t)b * CO * HW2;

    for (int c0 = 0; c0 < CO; c0 += 8) {
        for (int idx = tid; idx < 8 * 18 * 18; idx += 256) {
            int col = idx % 18;
            int tmp = idx / 18;
            int r = tmp % 18;
            int cc = tmp / 18;
            int gr = h0 - 1 + r, gc = w0 - 1 + col;
            float v = 0.f;
            if ((unsigned)gr < H2 && (unsigned)gc < W2)
                v = gb[(size_t)(c0 + cc) * HW2 + gr * W2 + gc];
            gs[cc][r][col] = v;
        }
        __syncthreads();
#pragma unroll
        for (int cc = 0; cc < 8; cc++) {
            float g0 = gs[cc][ly + 1][lx + 1];
#pragma unroll
            for (int di = 0; di < 3; di++)
#pragma unroll
                for (int dj = 0; dj < 3; dj++) {
                    float d = gs[cc][ly + di][lx + dj] - g0;
                    s[di * 3 + dj] = fmaf(d, d, s[di * 3 + dj]);
                }
        }
        __syncthreads();
    }

    const int h = h0 + ly, w = w0 + lx;
    float* kb = g_kf + (size_t)b * 9 * HW2;
#pragma unroll
    for (int t = 0; t < 9; t++) {
        int nh = h + t / 3 - 1, nw = w + t % 3 - 1;
        float v = ((unsigned)nh < H2 && (unsigned)nw < W2) ? expf(-0.5f * s[t]) : 0.f;
        kb[(size_t)t * HW2 + h * W2 + w] = v;
    }
}

// ---------------------------------------------------------------------------
// pac: tf32 MMA GEMM, kf folded into B operand.
// Block: M=128 co x N=128 pix (2 rows x 64 cols). K = 9 taps x 128 ci.
// ---------------------------------------------------------------------------
__global__ __launch_bounds__(256) void pac_mma(
    const float* __restrict__ b2, float* __restrict__ out)
{
    __shared__ __align__(16) uint32_t As[128 * 32];
    __shared__ __align__(16) uint32_t Bs[32 * 128];
    __shared__ float kfs[9 * 128];

    const int tid = threadIdx.x;
    const int lane = tid & 31, wid = tid >> 5;
    const int wm = (wid >> 2) * 64, wn = (wid & 3) * 32;
    const int b = blockIdx.z;
    const int h0 = blockIdx.y * 2;
    const int w0 = blockIdx.x * 64;

    // stage kf for this tile
    {
        const float* kb = g_kf + (size_t)b * 9 * HW2;
        for (int i = tid; i < 9 * 128; i += 256) {
            int pix = i & 127, t = i >> 7;
            kfs[i] = kb[(size_t)t * HW2 + (h0 + (pix >> 6)) * W2 + w0 + (pix & 63)];
        }
    }

    float acc[4][4][4];
#pragma unroll
    for (int mt = 0; mt < 4; mt++)
#pragma unroll
        for (int nt = 0; nt < 4; nt++)
#pragma unroll
            for (int r = 0; r < 4; r++) acc[mt][nt][r] = 0.f;

    const float* yb = g_y + (size_t)b * CO * HW2;
    const int lq = tid & 31, wq = tid >> 5;
    __syncthreads();

    for (int t = 0; t < 9; t++) {
        const int di = t / 3 - 1, dj = t % 3 - 1;
        for (int cch = 0; cch < 4; cch++) {
            // stage A
            {
                const uint4* src = (const uint4*)(g_w2s + (size_t)(t * 4 + cch) * 4096);
                uint4* dst = (uint4*)As;
#pragma unroll
                for (int j = 0; j < 4; j++) dst[tid + j * 256] = src[tid + j * 256];
            }
            // stage B: tf32(y * kf)
            {
                float kfv[4];
#pragma unroll
                for (int i = 0; i < 4; i++) kfv[i] = kfs[t * 128 + lq * 4 + i];
#pragma unroll
                for (int j = 0; j < 4; j++) {
                    const int k = wq * 4 + j;
                    const float* yrow = yb + (size_t)(cch * 32 + k) * HW2;
                    uint4 v;
                    uint32_t* vp = (uint32_t*)&v;
#pragma unroll
                    for (int i = 0; i < 4; i++) {
                        int pix = lq * 4 + i;
                        int h = h0 + (pix >> 6) + di;
                        int w = w0 + (pix & 63) + dj;
                        float yv = 0.f;
                        if ((unsigned)h < H2 && (unsigned)w < W2)
                            yv = __ldg(yrow + h * W2 + w);
                        vp[i] = f2tf32(yv * kfv[i]);
                    }
                    *(uint4*)&Bs[k * 128 + ((lq ^ (k & 7)) << 2)] = v;
                }
            }
            __syncthreads();
            gemm_chunk(As, Bs, acc, lane, wm, wn);
            __syncthreads();
        }
    }

    // epilogue
    float* ob = out + (size_t)b * CO * HW2;
    const int row = lane >> 2, col2 = (lane & 3) * 2;
#pragma unroll
    for (int mt = 0; mt < 4; mt++) {
        int co = wm + mt * 16 + row;
        float bv0 = __ldg(b2 + co);
        float bv1 = __ldg(b2 + co + 8);
#pragma unroll
        for (int nt = 0; nt < 4; nt++) {
            int pix = wn + nt * 8 + col2;
            int h = h0 + (pix >> 6), w = w0 + (pix & 63);
            float2 v0 = {acc[mt][nt][0] + bv0, acc[mt][nt][1] + bv0};
            float2 v1 = {acc[mt][nt][2] + bv1, acc[mt][nt][3] + bv1};
            *(float2*)(ob + (size_t)co * HW2 + h * W2 + w) = v0;
            *(float2*)(ob + (size_t)(co + 8) * HW2 + h * W2 + w) = v1;
        }
    }
}

// ---------------------------------------------------------------------------
extern "C" void kernel_launch(void* const* d_in, const int* in_sizes, int n_in,
                              void* d_out, int out_size)
{
    const float* x     = (const float*)d_in[0];
    const float* guide = (const float*)d_in[1];
    const float* w1    = (const float*)d_in[2];
    const float* b1    = (const float*)d_in[3];
    const float* w2    = (const float*)d_in[4];
    const float* b2    = (const float*)d_in[5];
    float* out = (float*)d_out;

    prep_w1s<<<(16 * CIN * CO + 255) / 256, 256>>>(w1);
    prep_w2s<<<(9 * 128 * 128 + 255) / 256, 256>>>(w2);
    conv1_mma<<<dim3(32, 4, 4), 256>>>(x, b1);
    kfac_kernel<<<dim3(8, 8, 4), 256>>>(guide);
    pac_mma<<<dim3(2, 64, 4), 256>>>(b2, out);
}